// round 13
// baseline (speedup 1.0000x reference)
#include <cuda_runtime.h>

#define NN 50000
#define EPC 256            // edges per tile (16 warps x 16 rows)
#define FTH 512

__device__ float g_P[(size_t)8 * NN * 64];
__device__ float g_agg[(size_t)NN * 64];

__device__ __forceinline__ float sigm_(float x) { return __fdividef(1.f, 1.f + __expf(-x)); }
__device__ __forceinline__ float silu_(float x) { return x * sigm_(x); }
__device__ __forceinline__ float tf32r(float x) {
    float y; asm("cvt.rna.tf32.f32 %0, %1;" : "=f"(y) : "f"(x)); return y;
}
__device__ __forceinline__ void pf2(const void* p) {
    asm volatile("prefetch.global.L2 [%0];" :: "l"(p));
}

// m16n8k8 tf32 HMMA, D += A*B (C==D)
__device__ __forceinline__ void mma8(float* d, const unsigned* a, const unsigned* b) {
    asm volatile("mma.sync.aligned.m16n8k8.row.col.f32.tf32.tf32.f32 "
        "{%0,%1,%2,%3},{%4,%5,%6,%7},{%8,%9},{%0,%1,%2,%3};"
        : "+f"(d[0]), "+f"(d[1]), "+f"(d[2]), "+f"(d[3])
        : "r"(a[0]), "r"(a[1]), "r"(a[2]), "r"(a[3]), "r"(b[0]), "r"(b[1]));
}

// ==================== projection kernel ====================
__global__ __launch_bounds__(256) void proj_mma_kernel(
    const float* __restrict__ nf, const float* __restrict__ eW1,
    const float* __restrict__ egW1, const float* __restrict__ nW1,
    const float* __restrict__ ngW1)
{
    extern __shared__ float sm[];
    float* sB = sm;           // 64 x 136
    float* sA = sm + 8704;    // 128 x 68

    int tid = threadIdx.x;
    int g = blockIdx.y;
    const float* W = (g == 0) ? eW1 : (g == 1) ? egW1 : (g == 2) ? nW1 : ngW1;
    int m0 = blockIdx.x * 128;

    for (int i = tid; i < 64 * 128; i += 256) {
        int k = i >> 7, n = i & 127;
        float v = (n < 64) ? W[k * 64 + n] : W[(128 + k) * 64 + (n - 64)];
        sB[k * 136 + n] = tf32r(v);
    }
    for (int i = tid; i < 128 * 64; i += 256) {
        int m = i >> 6, k = i & 63;
        int node = m0 + m;
        sA[m * 68 + k] = tf32r(node < NN ? nf[(size_t)node * 64 + k] : 0.f);
    }
    __syncthreads();

    int lane = tid & 31, w = tid >> 5, gid = lane >> 2, tig = lane & 3;
    int r0 = 16 * w + gid, r1 = r0 + 8;

    float acc[16][4];
    #pragma unroll
    for (int nt = 0; nt < 16; nt++)
        acc[nt][0] = acc[nt][1] = acc[nt][2] = acc[nt][3] = 0.f;

    #pragma unroll 2
    for (int kt = 0; kt < 8; kt++) {
        int k0 = kt * 8;
        unsigned a[4];
        a[0] = __float_as_uint(sA[r0 * 68 + k0 + tig]);
        a[1] = __float_as_uint(sA[r1 * 68 + k0 + tig]);
        a[2] = __float_as_uint(sA[r0 * 68 + k0 + tig + 4]);
        a[3] = __float_as_uint(sA[r1 * 68 + k0 + tig + 4]);
        const float* bp0 = sB + (k0 + tig) * 136 + gid;
        const float* bp1 = bp0 + 4 * 136;
        #pragma unroll
        for (int nt = 0; nt < 16; nt++) {
            unsigned b[2] = { __float_as_uint(bp0[8 * nt]), __float_as_uint(bp1[8 * nt]) };
            mma8(acc[nt], a, b);
        }
    }

    int n0g = m0 + r0, n1g = m0 + r1;
    #pragma unroll
    for (int nt = 0; nt < 16; nt++) {
        int slot = 2 * g + (nt >> 3);
        int c = ((nt & 7) << 3) + 2 * tig;
        float* base = g_P + (size_t)slot * NN * 64;
        if (n0g < NN) *(float2*)(base + (size_t)n0g * 64 + c) = make_float2(acc[nt][0], acc[nt][1]);
        if (n1g < NN) *(float2*)(base + (size_t)n1g * 64 + c) = make_float2(acc[nt][2], acc[nt][3]);
    }
}

__global__ void zero_agg_kernel() {
    size_t i = (size_t)blockIdx.x * 256 + threadIdx.x;
    if (i < (size_t)NN * 64) g_agg[i] = 0.f;
}

// ==================== single-pass fused kernel ====================
// 512 threads (16 warps), 1 CTA/SM persistent; per tile the edge update and
// node message run back-to-back; new_ef flows through SMEM. No __syncthreads
// in the tile loop (warp-private rows, read-only weights).
__global__ void __launch_bounds__(FTH, 1) fused_kernel(
    const float* __restrict__ ef, const int* __restrict__ src,
    const int* __restrict__ dst, const float* __restrict__ rbf,
    const float* __restrict__ sew, const float* __restrict__ snw,
    const float* __restrict__ eW1, const float* __restrict__ eb1,
    const float* __restrict__ eW2, const float* __restrict__ eb2,
    const float* __restrict__ egW1, const float* __restrict__ egb1,
    const float* __restrict__ egW2, const float* __restrict__ egb2,
    const float* __restrict__ nW1, const float* __restrict__ nb1,
    const float* __restrict__ nW2, const float* __restrict__ nb2,
    const float* __restrict__ ngW1, const float* __restrict__ ngb1,
    const float* __restrict__ ngW2, const float* __restrict__ ngb2,
    const float* __restrict__ ewf, const float* __restrict__ nwf,
    float* __restrict__ outEdge, int E, int nTiles)
{
    extern __shared__ float sm[];
    float* sB1e  = sm;             // 8704
    float* sB2e  = sm + 8704;      // 8704
    float* sB1n  = sm + 17408;     // 8704
    float* sB2n  = sm + 26112;     // 8704
    float* sSt   = sm + 34816;     // 256 x 68 = 17408
    float* sWFe  = sm + 52224;     // 576
    float* sWFn  = sm + 52800;     // 576
    float* sBias = sm + 53376;     // 512: eb1|egb1|eb2|egb2 | nb1|ngb1|nb2|ngb2
    // total 53888 floats = 215552 B -> 1 CTA/SM

    int tid = threadIdx.x, lane = tid & 31, w = tid >> 5;
    int gid = lane >> 2, tig = lane & 3;
    int r0 = 16 * w + gid, r1 = r0 + 8;
    float acc[16][4];

    for (int i = tid; i < 8192; i += FTH) {
        int k = i >> 7, n = i & 127;
        sB1e[k * 136 + n] = tf32r(n < 64 ? eW1[(64 + k) * 64 + n] : egW1[(64 + k) * 64 + (n - 64)]);
        sB2e[k * 136 + n] = tf32r(n < 64 ? eW2[k * 64 + n] : egW2[k * 64 + (n - 64)]);
        sB1n[k * 136 + n] = tf32r(n < 64 ? nW1[(64 + k) * 64 + n] : ngW1[(64 + k) * 64 + (n - 64)]);
        sB2n[k * 136 + n] = tf32r(n < 64 ? nW2[k * 64 + n] : ngW2[k * 64 + (n - 64)]);
    }
    for (int i = tid; i < 576; i += FTH) { sWFe[i] = ewf[i]; sWFn[i] = nwf[i]; }
    if (tid < 64) {
        sBias[tid]       = eb1[tid]; sBias[64 + tid]  = egb1[tid];
        sBias[128 + tid] = eb2[tid]; sBias[192 + tid] = egb2[tid];
        sBias[256 + tid] = nb1[tid]; sBias[320 + tid] = ngb1[tid];
        sBias[384 + tid] = nb2[tid]; sBias[448 + tid] = ngb2[tid];
    }
    __syncthreads();

    int t = blockIdx.x;
    int sn0 = 0, dn0 = 0, sn1 = 0, dn1 = 0;
    if (t < nTiles) {
        size_t en0 = (size_t)t * EPC + r0, en1 = (size_t)t * EPC + r1;
        if (en0 < (size_t)E) { sn0 = src[en0]; dn0 = dst[en0]; }
        if (en1 < (size_t)E) { sn1 = src[en1]; dn1 = dst[en1]; }
    }

    for (; t < nTiles; t += gridDim.x) {
        int s0 = sn0, d0 = dn0, s1 = sn1, d1 = dn1;
        int e0 = t * EPC;
        size_t eg0 = (size_t)e0 + r0, eg1 = (size_t)e0 + r1;
        bool v0 = eg0 < (size_t)E, v1 = eg1 < (size_t)E;
        int tn = t + gridDim.x;
        size_t en0 = 0, en1 = 0;
        if (tn < nTiles) {
            en0 = (size_t)tn * EPC + r0; en1 = (size_t)tn * EPC + r1;
            sn0 = dn0 = sn1 = dn1 = 0;
            if (en0 < (size_t)E) { sn0 = src[en0]; dn0 = dst[en0]; }
            if (en1 < (size_t)E) { sn1 = src[en1]; dn1 = dst[en1]; }
        }

        // ---------- stage ef rows (warp-private, tf32) ----------
        #pragma unroll
        for (int rr = 0; rr < 2; rr++) {
            int row = rr ? r1 : r0;
            size_t eg = rr ? eg1 : eg0;
            bool v = rr ? v1 : v0;
            #pragma unroll
            for (int q = 0; q < 4; q++) {
                float4 x = make_float4(0.f, 0.f, 0.f, 0.f);
                if (v) x = *(const float4*)(ef + eg * 64 + 16 * tig + 4 * q);
                float* dp = sSt + row * 68 + 16 * tig + 4 * q;
                dp[0] = tf32r(x.x); dp[1] = tf32r(x.y); dp[2] = tf32r(x.z); dp[3] = tf32r(x.w);
            }
        }

        // ---------- EDGE HALF ----------
        #pragma unroll
        for (int nt = 0; nt < 16; nt++) {
            int c = ((nt & 7) << 3) + 2 * tig;
            const float* Ai = g_P + (size_t)(nt < 8 ? 0 : 2) * NN * 64;
            const float* Aj = g_P + (size_t)(nt < 8 ? 1 : 3) * NN * 64;
            const float* bb = (nt < 8) ? sBias : (sBias + 64);
            float2 i0 = *(const float2*)(Ai + (size_t)s0 * 64 + c);
            float2 j0 = *(const float2*)(Aj + (size_t)d0 * 64 + c);
            float2 i1 = *(const float2*)(Ai + (size_t)s1 * 64 + c);
            float2 j1 = *(const float2*)(Aj + (size_t)d1 * 64 + c);
            float bx = bb[c], by = bb[c + 1];
            acc[nt][0] = i0.x + j0.x + bx; acc[nt][1] = i0.y + j0.y + by;
            acc[nt][2] = i1.x + j1.x + bx; acc[nt][3] = i1.y + j1.y + by;
        }
        __syncwarp();

        // phase1 (edge)
        #pragma unroll 2
        for (int kt = 0; kt < 8; kt++) {
            int k0 = 8 * kt;
            unsigned a[4];
            a[0] = __float_as_uint(sSt[r0 * 68 + k0 + tig]);
            a[1] = __float_as_uint(sSt[r1 * 68 + k0 + tig]);
            a[2] = __float_as_uint(sSt[r0 * 68 + k0 + tig + 4]);
            a[3] = __float_as_uint(sSt[r1 * 68 + k0 + tig + 4]);
            const float* bp0 = sB1e + (k0 + tig) * 136 + gid;
            const float* bp1 = bp0 + 4 * 136;
            #pragma unroll
            for (int nt = 0; nt < 16; nt++) {
                unsigned b[2] = { __float_as_uint(bp0[8 * nt]), __float_as_uint(bp1[8 * nt]) };
                mma8(acc[nt], a, b);
            }
        }

        // prefetch: this tile's node-slot rows (4-7), next tile's edge-slot rows + ef
        if (tig == 0) {
            pf2(g_P + (size_t)4 * NN * 64 + (size_t)s0 * 64 + 2 * gid);
            pf2(g_P + (size_t)5 * NN * 64 + (size_t)d0 * 64 + 2 * gid);
            pf2(g_P + (size_t)6 * NN * 64 + (size_t)s0 * 64 + 2 * gid);
            pf2(g_P + (size_t)7 * NN * 64 + (size_t)d0 * 64 + 2 * gid);
            pf2(g_P + (size_t)4 * NN * 64 + (size_t)s1 * 64 + 2 * gid);
            pf2(g_P + (size_t)5 * NN * 64 + (size_t)d1 * 64 + 2 * gid);
            pf2(g_P + (size_t)6 * NN * 64 + (size_t)s1 * 64 + 2 * gid);
            pf2(g_P + (size_t)7 * NN * 64 + (size_t)d1 * 64 + 2 * gid);
            if (tn < nTiles) {
                pf2(g_P + (size_t)0 * NN * 64 + (size_t)sn0 * 64 + 2 * gid);
                pf2(g_P + (size_t)1 * NN * 64 + (size_t)dn0 * 64 + 2 * gid);
                pf2(g_P + (size_t)2 * NN * 64 + (size_t)sn0 * 64 + 2 * gid);
                pf2(g_P + (size_t)3 * NN * 64 + (size_t)dn0 * 64 + 2 * gid);
                pf2(g_P + (size_t)0 * NN * 64 + (size_t)sn1 * 64 + 2 * gid);
                pf2(g_P + (size_t)1 * NN * 64 + (size_t)dn1 * 64 + 2 * gid);
                pf2(g_P + (size_t)2 * NN * 64 + (size_t)sn1 * 64 + 2 * gid);
                pf2(g_P + (size_t)3 * NN * 64 + (size_t)dn1 * 64 + 2 * gid);
                if (en0 < (size_t)E) pf2(ef + en0 * 64 + 2 * gid);
                if (en1 < (size_t)E) pf2(ef + en1 * 64 + 2 * gid);
            }
        }
        __syncwarp();

        // stage silu(h1)
        #pragma unroll
        for (int nt = 0; nt < 8; nt++) {
            int c = 8 * nt + 2 * tig;
            *(float2*)(sSt + r0 * 68 + c) = make_float2(tf32r(silu_(acc[nt][0])), tf32r(silu_(acc[nt][1])));
            *(float2*)(sSt + r1 * 68 + c) = make_float2(tf32r(silu_(acc[nt][2])), tf32r(silu_(acc[nt][3])));
            acc[nt][0] = acc[nt][1] = acc[nt][2] = acc[nt][3] = 0.f;
        }
        __syncwarp();
        // phase2-h (edge)
        #pragma unroll 2
        for (int kt = 0; kt < 8; kt++) {
            int k0 = 8 * kt;
            unsigned a[4];
            a[0] = __float_as_uint(sSt[r0 * 68 + k0 + tig]);
            a[1] = __float_as_uint(sSt[r1 * 68 + k0 + tig]);
            a[2] = __float_as_uint(sSt[r0 * 68 + k0 + tig + 4]);
            a[3] = __float_as_uint(sSt[r1 * 68 + k0 + tig + 4]);
            const float* bp0 = sB2e + (k0 + tig) * 136 + gid;
            const float* bp1 = bp0 + 4 * 136;
            #pragma unroll
            for (int nt = 0; nt < 8; nt++) {
                unsigned b[2] = { __float_as_uint(bp0[8 * nt]), __float_as_uint(bp1[8 * nt]) };
                mma8(acc[nt], a, b);
            }
        }
        __syncwarp();
        // stage silu(g1)
        #pragma unroll
        for (int nt = 8; nt < 16; nt++) {
            int c = 8 * (nt - 8) + 2 * tig;
            *(float2*)(sSt + r0 * 68 + c) = make_float2(tf32r(silu_(acc[nt][0])), tf32r(silu_(acc[nt][1])));
            *(float2*)(sSt + r1 * 68 + c) = make_float2(tf32r(silu_(acc[nt][2])), tf32r(silu_(acc[nt][3])));
            acc[nt][0] = acc[nt][1] = acc[nt][2] = acc[nt][3] = 0.f;
        }
        __syncwarp();
        // phase2-g (edge)
        #pragma unroll 2
        for (int kt = 0; kt < 8; kt++) {
            int k0 = 8 * kt;
            unsigned a[4];
            a[0] = __float_as_uint(sSt[r0 * 68 + k0 + tig]);
            a[1] = __float_as_uint(sSt[r1 * 68 + k0 + tig]);
            a[2] = __float_as_uint(sSt[r0 * 68 + k0 + tig + 4]);
            a[3] = __float_as_uint(sSt[r1 * 68 + k0 + tig + 4]);
            const float* bp0 = sB2e + (k0 + tig) * 136 + 64 + gid;
            const float* bp1 = bp0 + 4 * 136;
            #pragma unroll
            for (int nt = 8; nt < 16; nt++) {
                unsigned b[2] = { __float_as_uint(bp0[8 * (nt - 8)]), __float_as_uint(bp1[8 * (nt - 8)]) };
                mma8(acc[nt], a, b);
            }
        }
        __syncwarp();

        // edge epilogue: new_ef -> outEdge + sSt (tf32)
        float rb0[9], rb1[9];
        #pragma unroll
        for (int r = 0; r < 9; r++) {
            rb0[r] = v0 ? rbf[eg0 * 9 + r] : 0.f;
            rb1[r] = v1 ? rbf[eg1 * 9 + r] : 0.f;
        }
        #pragma unroll
        for (int nt = 0; nt < 8; nt++) {
            int c = 8 * nt + 2 * tig;
            float b2x = sBias[128 + c], b2y = sBias[128 + c + 1];
            float gbx = sBias[192 + c], gby = sBias[192 + c + 1];
            float h00 = silu_(acc[nt][0] + b2x), h01 = silu_(acc[nt][1] + b2y);
            float h10 = silu_(acc[nt][2] + b2x), h11 = silu_(acc[nt][3] + b2y);
            float g00 = sigm_(acc[nt + 8][0] + gbx), g01 = sigm_(acc[nt + 8][1] + gby);
            float g10 = sigm_(acc[nt + 8][2] + gbx), g11 = sigm_(acc[nt + 8][3] + gby);
            float wf00 = 0.f, wf01 = 0.f, wf10 = 0.f, wf11 = 0.f;
            #pragma unroll
            for (int r = 0; r < 9; r++) {
                float2 wv = *(const float2*)(sWFe + r * 64 + c);
                wf00 += rb0[r] * wv.x; wf01 += rb0[r] * wv.y;
                wf10 += rb1[r] * wv.x; wf11 += rb1[r] * wv.y;
            }
            float n00 = 0.f, n01 = 0.f, n10 = 0.f, n11 = 0.f;
            if (v0) {
                float2 swv = *(const float2*)(sew + eg0 * 64 + c);
                float2 ev  = *(const float2*)(ef + eg0 * 64 + c);
                n00 = ev.x + h00 * g00 * wf00 * swv.x;
                n01 = ev.y + h01 * g01 * wf01 * swv.y;
                *(float2*)(outEdge + eg0 * 64 + c) = make_float2(n00, n01);
            }
            if (v1) {
                float2 swv = *(const float2*)(sew + eg1 * 64 + c);
                float2 ev  = *(const float2*)(ef + eg1 * 64 + c);
                n10 = ev.x + h10 * g10 * wf10 * swv.x;
                n11 = ev.y + h11 * g11 * wf11 * swv.y;
                *(float2*)(outEdge + eg1 * 64 + c) = make_float2(n10, n11);
            }
            *(float2*)(sSt + r0 * 68 + c) = make_float2(tf32r(n00), tf32r(n01));
            *(float2*)(sSt + r1 * 68 + c) = make_float2(tf32r(n10), tf32r(n11));
        }
        __syncwarp();

        // ---------- NODE HALF ----------
        #pragma unroll
        for (int nt = 0; nt < 16; nt++) {
            int c = ((nt & 7) << 3) + 2 * tig;
            const float* Ai = g_P + (size_t)(nt < 8 ? 4 : 6) * NN * 64;
            const float* Aj = g_P + (size_t)(nt < 8 ? 5 : 7) * NN * 64;
            const float* bb = (nt < 8) ? (sBias + 256) : (sBias + 320);
            float2 i0 = *(const float2*)(Ai + (size_t)s0 * 64 + c);
            float2 j0 = *(const float2*)(Aj + (size_t)d0 * 64 + c);
            float2 i1 = *(const float2*)(Ai + (size_t)s1 * 64 + c);
            float2 j1 = *(const float2*)(Aj + (size_t)d1 * 64 + c);
            float bx = bb[c], by = bb[c + 1];
            acc[nt][0] = i0.x + j0.x + bx; acc[nt][1] = i0.y + j0.y + by;
            acc[nt][2] = i1.x + j1.x + bx; acc[nt][3] = i1.y + j1.y + by;
        }
        __syncwarp();

        // phase1 (node): A = new_ef from sSt
        #pragma unroll 2
        for (int kt = 0; kt < 8; kt++) {
            int k0 = 8 * kt;
            unsigned a[4];
            a[0] = __float_as_uint(sSt[r0 * 68 + k0 + tig]);
            a[1] = __float_as_uint(sSt[r1 * 68 + k0 + tig]);
            a[2] = __float_as_uint(sSt[r0 * 68 + k0 + tig + 4]);
            a[3] = __float_as_uint(sSt[r1 * 68 + k0 + tig + 4]);
            const float* bp0 = sB1n + (k0 + tig) * 136 + gid;
            const float* bp1 = bp0 + 4 * 136;
            #pragma unroll
            for (int nt = 0; nt < 16; nt++) {
                unsigned b[2] = { __float_as_uint(bp0[8 * nt]), __float_as_uint(bp1[8 * nt]) };
                mma8(acc[nt], a, b);
            }
        }
        __syncwarp();

        #pragma unroll
        for (int nt = 0; nt < 8; nt++) {
            int c = 8 * nt + 2 * tig;
            *(float2*)(sSt + r0 * 68 + c) = make_float2(tf32r(silu_(acc[nt][0])), tf32r(silu_(acc[nt][1])));
            *(float2*)(sSt + r1 * 68 + c) = make_float2(tf32r(silu_(acc[nt][2])), tf32r(silu_(acc[nt][3])));
            acc[nt][0] = acc[nt][1] = acc[nt][2] = acc[nt][3] = 0.f;
        }
        __syncwarp();
        // phase2-h (node)
        #pragma unroll 2
        for (int kt = 0; kt < 8; kt++) {
            int k0 = 8 * kt;
            unsigned a[4];
            a[0] = __float_as_uint(sSt[r0 * 68 + k0 + tig]);
            a[1] = __float_as_uint(sSt[r1 * 68 + k0 + tig]);
            a[2] = __float_as_uint(sSt[r0 * 68 + k0 + tig + 4]);
            a[3] = __float_as_uint(sSt[r1 * 68 + k0 + tig + 4]);
            const float* bp0 = sB2n + (k0 + tig) * 136 + gid;
            const float* bp1 = bp0 + 4 * 136;
            #pragma unroll
            for (int nt = 0; nt < 8; nt++) {
                unsigned b[2] = { __float_as_uint(bp0[8 * nt]), __float_as_uint(bp1[8 * nt]) };
                mma8(acc[nt], a, b);
            }
        }
        __syncwarp();
        #pragma unroll
        for (int nt = 8; nt < 16; nt++) {
            int c = 8 * (nt - 8) + 2 * tig;
            *(float2*)(sSt + r0 * 68 + c) = make_float2(tf32r(silu_(acc[nt][0])), tf32r(silu_(acc[nt][1])));
            *(float2*)(sSt + r1 * 68 + c) = make_float2(tf32r(silu_(acc[nt][2])), tf32r(silu_(acc[nt][3])));
            acc[nt][0] = acc[nt][1] = acc[nt][2] = acc[nt][3] = 0.f;
        }
        __syncwarp();
        // phase2-g (node)
        #pragma unroll 2
        for (int kt = 0; kt < 8; kt++) {
            int k0 = 8 * kt;
            unsigned a[4];
            a[0] = __float_as_uint(sSt[r0 * 68 + k0 + tig]);
            a[1] = __float_as_uint(sSt[r1 * 68 + k0 + tig]);
            a[2] = __float_as_uint(sSt[r0 * 68 + k0 + tig + 4]);
            a[3] = __float_as_uint(sSt[r1 * 68 + k0 + tig + 4]);
            const float* bp0 = sB2n + (k0 + tig) * 136 + 64 + gid;
            const float* bp1 = bp0 + 4 * 136;
            #pragma unroll
            for (int nt = 8; nt < 16; nt++) {
                unsigned b[2] = { __float_as_uint(bp0[8 * (nt - 8)]), __float_as_uint(bp1[8 * (nt - 8)]) };
                mma8(acc[nt], a, b);
            }
        }

        // node epilogue: atomics
        #pragma unroll
        for (int nt = 0; nt < 8; nt++) {
            int c = 8 * nt + 2 * tig;
            float b2x = sBias[384 + c], b2y = sBias[384 + c + 1];
            float gbx = sBias[448 + c], gby = sBias[448 + c + 1];
            float h00 = silu_(acc[nt][0] + b2x), h01 = silu_(acc[nt][1] + b2y);
            float h10 = silu_(acc[nt][2] + b2x), h11 = silu_(acc[nt][3] + b2y);
            float g00 = sigm_(acc[nt + 8][0] + gbx), g01 = sigm_(acc[nt + 8][1] + gby);
            float g10 = sigm_(acc[nt + 8][2] + gbx), g11 = sigm_(acc[nt + 8][3] + gby);
            float wf00 = 0.f, wf01 = 0.f, wf10 = 0.f, wf11 = 0.f;
            #pragma unroll
            for (int r = 0; r < 9; r++) {
                float2 wv = *(const float2*)(sWFn + r * 64 + c);
                wf00 += rb0[r] * wv.x; wf01 += rb0[r] * wv.y;
                wf10 += rb1[r] * wv.x; wf11 += rb1[r] * wv.y;
            }
            if (v0) {
                float2 swv = *(const float2*)(snw + eg0 * 64 + c);
                atomicAdd(&g_agg[(size_t)d0 * 64 + c],     h00 * g00 * wf00 * swv.x);
                atomicAdd(&g_agg[(size_t)d0 * 64 + c + 1], h01 * g01 * wf01 * swv.y);
            }
            if (v1) {
                float2 swv = *(const float2*)(snw + eg1 * 64 + c);
                atomicAdd(&g_agg[(size_t)d1 * 64 + c],     h10 * g10 * wf10 * swv.x);
                atomicAdd(&g_agg[(size_t)d1 * 64 + c + 1], h11 * g11 * wf11 * swv.y);
            }
        }
        __syncwarp();
    }
}

// ==================== node output ====================
__global__ __launch_bounds__(256) void nodeout_kernel(
    const float* __restrict__ nf, const float* __restrict__ Wout,
    float* __restrict__ out)
{
    __shared__ float sAG[4096];
    __shared__ float sW[4096];
    int tid = threadIdx.x;
    int m0 = blockIdx.x * 64;
    for (int i = tid; i < 1024; i += 256) {
        ((float4*)sW)[i] = ((const float4*)Wout)[i];
        int m = i >> 4;
        float4 v = make_float4(0.f, 0.f, 0.f, 0.f);
        if (m0 + m < NN) v = *(const float4*)&g_agg[(size_t)(m0 + m) * 64 + 4 * (i & 15)];
        ((float4*)sAG)[i] = v;
    }
    __syncthreads();
    int tx = tid & 15, ty = tid >> 4, n0 = 4 * tx;
    float acc[4][4] = {};
    #pragma unroll 16
    for (int k = 0; k < 64; k++) {
        float a0 = sAG[(4*ty+0)*64+k], a1 = sAG[(4*ty+1)*64+k];
        float a2 = sAG[(4*ty+2)*64+k], a3 = sAG[(4*ty+3)*64+k];
        float4 b = *(const float4*)&sW[k * 64 + n0];
        acc[0][0]+=a0*b.x; acc[0][1]+=a0*b.y; acc[0][2]+=a0*b.z; acc[0][3]+=a0*b.w;
        acc[1][0]+=a1*b.x; acc[1][1]+=a1*b.y; acc[1][2]+=a1*b.z; acc[1][3]+=a1*b.w;
        acc[2][0]+=a2*b.x; acc[2][1]+=a2*b.y; acc[2][2]+=a2*b.z; acc[2][3]+=a2*b.w;
        acc[3][0]+=a3*b.x; acc[3][1]+=a3*b.y; acc[3][2]+=a3*b.z; acc[3][3]+=a3*b.w;
    }
    #pragma unroll
    for (int i = 0; i < 4; i++) {
        int m = m0 + 4 * ty + i;
        if (m < NN) {
            float4 base = *(const float4*)&nf[(size_t)m * 64 + n0];
            *(float4*)&out[(size_t)m * 64 + n0] = make_float4(
                base.x + acc[i][0], base.y + acc[i][1], base.z + acc[i][2], base.w + acc[i][3]);
        }
    }
}

// ==================== launch ====================
extern "C" void kernel_launch(void* const* d_in, const int* in_sizes, int n_in,
                              void* d_out, int out_size) {
    const float* nf   = (const float*)d_in[0];
    const float* ef   = (const float*)d_in[1];
    const int*   src  = (const int*)d_in[2];
    const int*   dst  = (const int*)d_in[3];
    const float* rbf  = (const float*)d_in[4];
    const float* snw  = (const float*)d_in[5];
    const float* sew  = (const float*)d_in[6];
    const float* eW1  = (const float*)d_in[7];
    const float* eb1  = (const float*)d_in[8];
    const float* eW2  = (const float*)d_in[9];
    const float* eb2  = (const float*)d_in[10];
    const float* egW1 = (const float*)d_in[11];
    const float* egb1 = (const float*)d_in[12];
    const float* egW2 = (const float*)d_in[13];
    const float* egb2 = (const float*)d_in[14];
    const float* nW1  = (const float*)d_in[15];
    const float* nb1  = (const float*)d_in[16];
    const float* nW2  = (const float*)d_in[17];
    const float* nb2  = (const float*)d_in[18];
    const float* ngW1 = (const float*)d_in[19];
    const float* ngb1 = (const float*)d_in[20];
    const float* ngW2 = (const float*)d_in[21];
    const float* ngb2 = (const float*)d_in[22];
    const float* WoutM = (const float*)d_in[23];
    const float* nwf  = (const float*)d_in[24];
    const float* ewf  = (const float*)d_in[25];

    int E = in_sizes[2];
    float* outNode = (float*)d_out;
    float* outEdge = outNode + (size_t)NN * 64;

    const int FSM = 53888 * 4;   // 215552 B -> 1 CTA/SM
    const int PSM = 17408 * 4;
    static int sms = 0;
    if (!sms) {
        cudaFuncSetAttribute(fused_kernel, cudaFuncAttributeMaxDynamicSharedMemorySize, FSM);
        cudaFuncSetAttribute(proj_mma_kernel, cudaFuncAttributeMaxDynamicSharedMemorySize, PSM);
        cudaDeviceGetAttribute(&sms, cudaDevAttrMultiProcessorCount, 0);
        if (sms <= 0) sms = 148;
    }

    dim3 gP((NN + 127) / 128, 4);
    proj_mma_kernel<<<gP, 256, PSM>>>(nf, eW1, egW1, nW1, ngW1);

    zero_agg_kernel<<<((size_t)NN * 64 + 255) / 256, 256>>>();

    int nTiles = (E + EPC - 1) / EPC;
    int grid = nTiles < sms ? nTiles : sms;
    fused_kernel<<<grid, FTH, FSM>>>(
        ef, src, dst, rbf, sew, snw,
        eW1, eb1, eW2, eb2, egW1, egb1, egW2, egb2,
        nW1, nb1, nW2, nb2, ngW1, ngb1, ngW2, ngb2,
        ewf, nwf, outEdge, E, nTiles);

    nodeout_kernel<<<(NN + 63) / 64, 256>>>(nf, WoutM, outNode);
}

// round 14
// speedup vs baseline: 1.0846x; 1.0846x over previous
#include <cuda_runtime.h>

#define NN 50000
#define EPC 128
#define GRID_F 296   // exactly 2 CTAs/SM on 148 SMs

__device__ float g_P[(size_t)8 * NN * 64];
__device__ float g_agg[(size_t)NN * 64];

__device__ __forceinline__ float sigm_(float x) { return __fdividef(1.f, 1.f + __expf(-x)); }
__device__ __forceinline__ float silu_(float x) { return x * sigm_(x); }
__device__ __forceinline__ float tf32r(float x) {
    float y; asm("cvt.rna.tf32.f32 %0, %1;" : "=f"(y) : "f"(x)); return y;
}
__device__ __forceinline__ void pf2(const void* p) {
    asm volatile("prefetch.global.L2 [%0];" :: "l"(p));
}
// vectorized fire-and-forget atomic add (sm_90+): one REDG for a float2
__device__ __forceinline__ void red2(float* p, float x, float y) {
    asm volatile("red.global.add.v2.f32 [%0], {%1, %2};" :: "l"(p), "f"(x), "f"(y) : "memory");
}

// m16n8k8 tf32 HMMA, D += A*B (C==D)
__device__ __forceinline__ void mma8(float* d, const unsigned* a, const unsigned* b) {
    asm volatile("mma.sync.aligned.m16n8k8.row.col.f32.tf32.tf32.f32 "
        "{%0,%1,%2,%3},{%4,%5,%6,%7},{%8,%9},{%0,%1,%2,%3};"
        : "+f"(d[0]), "+f"(d[1]), "+f"(d[2]), "+f"(d[3])
        : "r"(a[0]), "r"(a[1]), "r"(a[2]), "r"(a[3]), "r"(b[0]), "r"(b[1]));
}

// ==================== projection kernel (also zeroes g_agg) ====================
__global__ __launch_bounds__(256) void proj_mma_kernel(
    const float* __restrict__ nf, const float* __restrict__ eW1,
    const float* __restrict__ egW1, const float* __restrict__ nW1,
    const float* __restrict__ ngW1)
{
    extern __shared__ float sm[];
    float* sB = sm;           // 64 x 136
    float* sA = sm + 8704;    // 128 x 68

    int tid = threadIdx.x;
    int g = blockIdx.y;
    const float* W = (g == 0) ? eW1 : (g == 1) ? egW1 : (g == 2) ? nW1 : ngW1;
    int m0 = blockIdx.x * 128;

    // fold g_agg zeroing in: 391x4 blocks x 256 threads cover 3.2M floats
    {
        size_t nblk = (size_t)gridDim.x * 4;
        size_t bid = (size_t)blockIdx.y * gridDim.x + blockIdx.x;
        size_t total = (size_t)NN * 64;
        size_t per = (total + nblk - 1) / nblk;
        size_t i0 = bid * per, i1 = i0 + per;
        if (i1 > total) i1 = total;
        for (size_t i = i0 + tid; i < i1; i += 256) g_agg[i] = 0.f;
    }

    for (int i = tid; i < 64 * 128; i += 256) {
        int k = i >> 7, n = i & 127;
        float v = (n < 64) ? W[k * 64 + n] : W[(128 + k) * 64 + (n - 64)];
        sB[k * 136 + n] = tf32r(v);
    }
    for (int i = tid; i < 128 * 64; i += 256) {
        int m = i >> 6, k = i & 63;
        int node = m0 + m;
        sA[m * 68 + k] = tf32r(node < NN ? nf[(size_t)node * 64 + k] : 0.f);
    }
    __syncthreads();

    int lane = tid & 31, w = tid >> 5, gid = lane >> 2, tig = lane & 3;
    int r0 = 16 * w + gid, r1 = r0 + 8;

    float acc[16][4];
    #pragma unroll
    for (int nt = 0; nt < 16; nt++)
        acc[nt][0] = acc[nt][1] = acc[nt][2] = acc[nt][3] = 0.f;

    #pragma unroll 2
    for (int kt = 0; kt < 8; kt++) {
        int k0 = kt * 8;
        unsigned a[4];
        a[0] = __float_as_uint(sA[r0 * 68 + k0 + tig]);
        a[1] = __float_as_uint(sA[r1 * 68 + k0 + tig]);
        a[2] = __float_as_uint(sA[r0 * 68 + k0 + tig + 4]);
        a[3] = __float_as_uint(sA[r1 * 68 + k0 + tig + 4]);
        const float* bp0 = sB + (k0 + tig) * 136 + gid;
        const float* bp1 = bp0 + 4 * 136;
        #pragma unroll
        for (int nt = 0; nt < 16; nt++) {
            unsigned b[2] = { __float_as_uint(bp0[8 * nt]), __float_as_uint(bp1[8 * nt]) };
            mma8(acc[nt], a, b);
        }
    }

    int n0g = m0 + r0, n1g = m0 + r1;
    #pragma unroll
    for (int nt = 0; nt < 16; nt++) {
        int slot = 2 * g + (nt >> 3);
        int c = ((nt & 7) << 3) + 2 * tig;
        float* base = g_P + (size_t)slot * NN * 64;
        if (n0g < NN) *(float2*)(base + (size_t)n0g * 64 + c) = make_float2(acc[nt][0], acc[nt][1]);
        if (n1g < NN) *(float2*)(base + (size_t)n1g * 64 + c) = make_float2(acc[nt][2], acc[nt][3]);
    }
}

// ==================== fused persistent edge+node kernel ====================
__global__ void __launch_bounds__(256, 2) fused_kernel(
    const float* __restrict__ ef, const int* __restrict__ src,
    const int* __restrict__ dst, const float* __restrict__ rbf,
    const float* __restrict__ sew, const float* __restrict__ snw,
    const float* __restrict__ eW1, const float* __restrict__ eb1,
    const float* __restrict__ eW2, const float* __restrict__ eb2,
    const float* __restrict__ egW1, const float* __restrict__ egb1,
    const float* __restrict__ egW2, const float* __restrict__ egb2,
    const float* __restrict__ nW1, const float* __restrict__ nb1,
    const float* __restrict__ nW2, const float* __restrict__ nb2,
    const float* __restrict__ ngW1, const float* __restrict__ ngb1,
    const float* __restrict__ ngW2, const float* __restrict__ ngb2,
    const float* __restrict__ ewf, const float* __restrict__ nwf,
    float* __restrict__ outEdge, int E, int nTiles)
{
    extern __shared__ float sm[];
    float* sB1   = sm;            // 8704
    float* sB2   = sm + 8704;     // 8704
    float* sSt   = sm + 17408;    // 8704: warp-private stage
    float* sWF   = sm + 26112;    // 576
    float* sBias = sm + 26688;    // 256
    // total 26944 floats = 107776 B -> 2 CTAs/SM

    int tid = threadIdx.x, lane = tid & 31, w = tid >> 5;
    int gid = lane >> 2, tig = lane & 3;
    int r0 = 16 * w + gid, r1 = r0 + 8;
    float acc[16][4];

    for (int i = tid; i < 8192; i += 256) {
        int k = i >> 7, n = i & 127;
        sB1[k * 136 + n] = tf32r(n < 64 ? eW1[(64 + k) * 64 + n] : egW1[(64 + k) * 64 + (n - 64)]);
        sB2[k * 136 + n] = tf32r(n < 64 ? eW2[k * 64 + n] : egW2[k * 64 + (n - 64)]);
    }
    for (int i = tid; i < 576; i += 256) sWF[i] = ewf[i];
    if (tid < 64) {
        sBias[tid] = eb1[tid]; sBias[64 + tid] = egb1[tid];
        sBias[128 + tid] = eb2[tid]; sBias[192 + tid] = egb2[tid];
    }
    __syncthreads();

    // ================= EDGE PASS =================
    {
        int t = blockIdx.x;
        int sn0 = 0, dn0 = 0, sn1 = 0, dn1 = 0;
        if (t < nTiles) {
            size_t en0 = (size_t)t * EPC + r0, en1 = (size_t)t * EPC + r1;
            if (en0 < (size_t)E) { sn0 = src[en0]; dn0 = dst[en0]; }
            if (en1 < (size_t)E) { sn1 = src[en1]; dn1 = dst[en1]; }
        }
        for (; t < nTiles; t += gridDim.x) {
            int s0 = sn0, d0 = dn0, s1 = sn1, d1 = dn1;
            int e0 = t * EPC;
            size_t eg0 = (size_t)e0 + r0, eg1 = (size_t)e0 + r1;
            bool v0 = eg0 < (size_t)E, v1 = eg1 < (size_t)E;
            int tn = t + gridDim.x;
            size_t en0 = 0, en1 = 0;
            if (tn < nTiles) {
                en0 = (size_t)tn * EPC + r0; en1 = (size_t)tn * EPC + r1;
                sn0 = dn0 = sn1 = dn1 = 0;
                if (en0 < (size_t)E) { sn0 = src[en0]; dn0 = dst[en0]; }
                if (en1 < (size_t)E) { sn1 = src[en1]; dn1 = dst[en1]; }
            }

            // stage ef rows (warp-private)
            #pragma unroll
            for (int rr = 0; rr < 2; rr++) {
                int row = rr ? r1 : r0;
                size_t eg = rr ? eg1 : eg0;
                bool v = rr ? v1 : v0;
                #pragma unroll
                for (int q = 0; q < 4; q++) {
                    float4 x = make_float4(0.f, 0.f, 0.f, 0.f);
                    if (v) x = *(const float4*)(ef + eg * 64 + 16 * tig + 4 * q);
                    float* dp = sSt + row * 68 + 16 * tig + 4 * q;
                    dp[0] = tf32r(x.x); dp[1] = tf32r(x.y); dp[2] = tf32r(x.z); dp[3] = tf32r(x.w);
                }
            }

            // C-init
            #pragma unroll
            for (int nt = 0; nt < 16; nt++) {
                int c = ((nt & 7) << 3) + 2 * tig;
                const float* Ai = g_P + (size_t)(nt < 8 ? 0 : 2) * NN * 64;
                const float* Aj = g_P + (size_t)(nt < 8 ? 1 : 3) * NN * 64;
                const float* bb = (nt < 8) ? sBias : (sBias + 64);
                float2 i0 = *(const float2*)(Ai + (size_t)s0 * 64 + c);
                float2 j0 = *(const float2*)(Aj + (size_t)d0 * 64 + c);
                float2 i1 = *(const float2*)(Ai + (size_t)s1 * 64 + c);
                float2 j1 = *(const float2*)(Aj + (size_t)d1 * 64 + c);
                float bx = bb[c], by = bb[c + 1];
                acc[nt][0] = i0.x + j0.x + bx; acc[nt][1] = i0.y + j0.y + by;
                acc[nt][2] = i1.x + j1.x + bx; acc[nt][3] = i1.y + j1.y + by;
            }
            __syncwarp();

            // phase1
            #pragma unroll 2
            for (int kt = 0; kt < 8; kt++) {
                int k0 = 8 * kt;
                unsigned a[4];
                a[0] = __float_as_uint(sSt[r0 * 68 + k0 + tig]);
                a[1] = __float_as_uint(sSt[r1 * 68 + k0 + tig]);
                a[2] = __float_as_uint(sSt[r0 * 68 + k0 + tig + 4]);
                a[3] = __float_as_uint(sSt[r1 * 68 + k0 + tig + 4]);
                const float* bp0 = sB1 + (k0 + tig) * 136 + gid;
                const float* bp1 = bp0 + 4 * 136;
                #pragma unroll
                for (int nt = 0; nt < 16; nt++) {
                    unsigned b[2] = { __float_as_uint(bp0[8 * nt]), __float_as_uint(bp1[8 * nt]) };
                    mma8(acc[nt], a, b);
                }
            }

            // prefetch next tile's gather rows + ef rows
            if (tn < nTiles && tig == 0) {
                pf2(g_P + (size_t)0 * NN * 64 + (size_t)sn0 * 64 + 2 * gid);
                pf2(g_P + (size_t)1 * NN * 64 + (size_t)dn0 * 64 + 2 * gid);
                pf2(g_P + (size_t)2 * NN * 64 + (size_t)sn0 * 64 + 2 * gid);
                pf2(g_P + (size_t)3 * NN * 64 + (size_t)dn0 * 64 + 2 * gid);
                pf2(g_P + (size_t)0 * NN * 64 + (size_t)sn1 * 64 + 2 * gid);
                pf2(g_P + (size_t)1 * NN * 64 + (size_t)dn1 * 64 + 2 * gid);
                pf2(g_P + (size_t)2 * NN * 64 + (size_t)sn1 * 64 + 2 * gid);
                pf2(g_P + (size_t)3 * NN * 64 + (size_t)dn1 * 64 + 2 * gid);
                if (en0 < (size_t)E) pf2(ef + en0 * 64 + 2 * gid);
                if (en1 < (size_t)E) pf2(ef + en1 * 64 + 2 * gid);
            }
            __syncwarp();

            // stage silu(h1)
            #pragma unroll
            for (int nt = 0; nt < 8; nt++) {
                int c = 8 * nt + 2 * tig;
                *(float2*)(sSt + r0 * 68 + c) = make_float2(tf32r(silu_(acc[nt][0])), tf32r(silu_(acc[nt][1])));
                *(float2*)(sSt + r1 * 68 + c) = make_float2(tf32r(silu_(acc[nt][2])), tf32r(silu_(acc[nt][3])));
                acc[nt][0] = acc[nt][1] = acc[nt][2] = acc[nt][3] = 0.f;
            }
            __syncwarp();
            // phase2-h
            #pragma unroll 2
            for (int kt = 0; kt < 8; kt++) {
                int k0 = 8 * kt;
                unsigned a[4];
                a[0] = __float_as_uint(sSt[r0 * 68 + k0 + tig]);
                a[1] = __float_as_uint(sSt[r1 * 68 + k0 + tig]);
                a[2] = __float_as_uint(sSt[r0 * 68 + k0 + tig + 4]);
                a[3] = __float_as_uint(sSt[r1 * 68 + k0 + tig + 4]);
                const float* bp0 = sB2 + (k0 + tig) * 136 + gid;
                const float* bp1 = bp0 + 4 * 136;
                #pragma unroll
                for (int nt = 0; nt < 8; nt++) {
                    unsigned b[2] = { __float_as_uint(bp0[8 * nt]), __float_as_uint(bp1[8 * nt]) };
                    mma8(acc[nt], a, b);
                }
            }
            __syncwarp();
            // stage silu(g1)
            #pragma unroll
            for (int nt = 8; nt < 16; nt++) {
                int c = 8 * (nt - 8) + 2 * tig;
                *(float2*)(sSt + r0 * 68 + c) = make_float2(tf32r(silu_(acc[nt][0])), tf32r(silu_(acc[nt][1])));
                *(float2*)(sSt + r1 * 68 + c) = make_float2(tf32r(silu_(acc[nt][2])), tf32r(silu_(acc[nt][3])));
                acc[nt][0] = acc[nt][1] = acc[nt][2] = acc[nt][3] = 0.f;
            }
            __syncwarp();
            // phase2-g
            #pragma unroll 2
            for (int kt = 0; kt < 8; kt++) {
                int k0 = 8 * kt;
                unsigned a[4];
                a[0] = __float_as_uint(sSt[r0 * 68 + k0 + tig]);
                a[1] = __float_as_uint(sSt[r1 * 68 + k0 + tig]);
                a[2] = __float_as_uint(sSt[r0 * 68 + k0 + tig + 4]);
                a[3] = __float_as_uint(sSt[r1 * 68 + k0 + tig + 4]);
                const float* bp0 = sB2 + (k0 + tig) * 136 + 64 + gid;
                const float* bp1 = bp0 + 4 * 136;
                #pragma unroll
                for (int nt = 8; nt < 16; nt++) {
                    unsigned b[2] = { __float_as_uint(bp0[8 * (nt - 8)]), __float_as_uint(bp1[8 * (nt - 8)]) };
                    mma8(acc[nt], a, b);
                }
            }

            // epilogue
            float rb0[9], rb1[9];
            #pragma unroll
            for (int r = 0; r < 9; r++) {
                rb0[r] = v0 ? rbf[eg0 * 9 + r] : 0.f;
                rb1[r] = v1 ? rbf[eg1 * 9 + r] : 0.f;
            }
            #pragma unroll
            for (int nt = 0; nt < 8; nt++) {
                int c = 8 * nt + 2 * tig;
                float b2x = sBias[128 + c], b2y = sBias[128 + c + 1];
                float gbx = sBias[192 + c], gby = sBias[192 + c + 1];
                float h00 = silu_(acc[nt][0] + b2x), h01 = silu_(acc[nt][1] + b2y);
                float h10 = silu_(acc[nt][2] + b2x), h11 = silu_(acc[nt][3] + b2y);
                float g00 = sigm_(acc[nt + 8][0] + gbx), g01 = sigm_(acc[nt + 8][1] + gby);
                float g10 = sigm_(acc[nt + 8][2] + gbx), g11 = sigm_(acc[nt + 8][3] + gby);
                float wf00 = 0.f, wf01 = 0.f, wf10 = 0.f, wf11 = 0.f;
                #pragma unroll
                for (int r = 0; r < 9; r++) {
                    float2 wv = *(const float2*)(sWF + r * 64 + c);
                    wf00 += rb0[r] * wv.x; wf01 += rb0[r] * wv.y;
                    wf10 += rb1[r] * wv.x; wf11 += rb1[r] * wv.y;
                }
                if (v0) {
                    float2 swv = *(const float2*)(sew + eg0 * 64 + c);
                    float2 ev  = *(const float2*)(ef + eg0 * 64 + c);
                    *(float2*)(outEdge + eg0 * 64 + c) = make_float2(
                        ev.x + h00 * g00 * wf00 * swv.x, ev.y + h01 * g01 * wf01 * swv.y);
                }
                if (v1) {
                    float2 swv = *(const float2*)(sew + eg1 * 64 + c);
                    float2 ev  = *(const float2*)(ef + eg1 * 64 + c);
                    *(float2*)(outEdge + eg1 * 64 + c) = make_float2(
                        ev.x + h10 * g10 * wf10 * swv.x, ev.y + h11 * g11 * wf11 * swv.y);
                }
            }
            __syncwarp();
        }
    }

    // ---- swap to node-phase weights ----
    __syncthreads();
    for (int i = tid; i < 8192; i += 256) {
        int k = i >> 7, n = i & 127;
        sB1[k * 136 + n] = tf32r(n < 64 ? nW1[(64 + k) * 64 + n] : ngW1[(64 + k) * 64 + (n - 64)]);
        sB2[k * 136 + n] = tf32r(n < 64 ? nW2[k * 64 + n] : ngW2[k * 64 + (n - 64)]);
    }
    for (int i = tid; i < 576; i += 256) sWF[i] = nwf[i];
    if (tid < 64) {
        sBias[tid] = nb1[tid]; sBias[64 + tid] = ngb1[tid];
        sBias[128 + tid] = nb2[tid]; sBias[192 + tid] = ngb2[tid];
    }
    __syncthreads();

    // ================= NODE PASS =================
    {
        int t = blockIdx.x;
        int sn0 = 0, dn0 = 0, sn1 = 0, dn1 = 0;
        if (t < nTiles) {
            size_t en0 = (size_t)t * EPC + r0, en1 = (size_t)t * EPC + r1;
            if (en0 < (size_t)E) { sn0 = src[en0]; dn0 = dst[en0]; }
            if (en1 < (size_t)E) { sn1 = src[en1]; dn1 = dst[en1]; }
        }
        for (int t2 = t; t2 < nTiles; t2 += gridDim.x) {
            int s0 = sn0, d0 = dn0, s1 = sn1, d1 = dn1;
            int e0 = t2 * EPC;
            size_t eg0 = (size_t)e0 + r0, eg1 = (size_t)e0 + r1;
            bool v0 = eg0 < (size_t)E, v1 = eg1 < (size_t)E;
            int tn = t2 + gridDim.x;
            size_t en0 = 0, en1 = 0;
            if (tn < nTiles) {
                en0 = (size_t)tn * EPC + r0; en1 = (size_t)tn * EPC + r1;
                sn0 = dn0 = sn1 = dn1 = 0;
                if (en0 < (size_t)E) { sn0 = src[en0]; dn0 = dst[en0]; }
                if (en1 < (size_t)E) { sn1 = src[en1]; dn1 = dst[en1]; }
            }

            // stage new_ef rows from outEdge
            #pragma unroll
            for (int rr = 0; rr < 2; rr++) {
                int row = rr ? r1 : r0;
                size_t eg = rr ? eg1 : eg0;
                bool v = rr ? v1 : v0;
                #pragma unroll
                for (int q = 0; q < 4; q++) {
                    float4 x = make_float4(0.f, 0.f, 0.f, 0.f);
                    if (v) x = *(const float4*)(outEdge + eg * 64 + 16 * tig + 4 * q);
                    float* dp = sSt + row * 68 + 16 * tig + 4 * q;
                    dp[0] = tf32r(x.x); dp[1] = tf32r(x.y); dp[2] = tf32r(x.z); dp[3] = tf32r(x.w);
                }
            }

            #pragma unroll
            for (int nt = 0; nt < 16; nt++) {
                int c = ((nt & 7) << 3) + 2 * tig;
                const float* Ai = g_P + (size_t)(nt < 8 ? 4 : 6) * NN * 64;
                const float* Aj = g_P + (size_t)(nt < 8 ? 5 : 7) * NN * 64;
                const float* bb = (nt < 8) ? sBias : (sBias + 64);
                float2 i0 = *(const float2*)(Ai + (size_t)s0 * 64 + c);
                float2 j0 = *(const float2*)(Aj + (size_t)d0 * 64 + c);
                float2 i1 = *(const float2*)(Ai + (size_t)s1 * 64 + c);
                float2 j1 = *(const float2*)(Aj + (size_t)d1 * 64 + c);
                float bx = bb[c], by = bb[c + 1];
                acc[nt][0] = i0.x + j0.x + bx; acc[nt][1] = i0.y + j0.y + by;
                acc[nt][2] = i1.x + j1.x + bx; acc[nt][3] = i1.y + j1.y + by;
            }
            __syncwarp();

            #pragma unroll 2
            for (int kt = 0; kt < 8; kt++) {
                int k0 = 8 * kt;
                unsigned a[4];
                a[0] = __float_as_uint(sSt[r0 * 68 + k0 + tig]);
                a[1] = __float_as_uint(sSt[r1 * 68 + k0 + tig]);
                a[2] = __float_as_uint(sSt[r0 * 68 + k0 + tig + 4]);
                a[3] = __float_as_uint(sSt[r1 * 68 + k0 + tig + 4]);
                const float* bp0 = sB1 + (k0 + tig) * 136 + gid;
                const float* bp1 = bp0 + 4 * 136;
                #pragma unroll
                for (int nt = 0; nt < 16; nt++) {
                    unsigned b[2] = { __float_as_uint(bp0[8 * nt]), __float_as_uint(bp1[8 * nt]) };
                    mma8(acc[nt], a, b);
                }
            }

            if (tn < nTiles && tig == 0) {
                pf2(g_P + (size_t)4 * NN * 64 + (size_t)sn0 * 64 + 2 * gid);
                pf2(g_P + (size_t)5 * NN * 64 + (size_t)dn0 * 64 + 2 * gid);
                pf2(g_P + (size_t)6 * NN * 64 + (size_t)sn0 * 64 + 2 * gid);
                pf2(g_P + (size_t)7 * NN * 64 + (size_t)dn0 * 64 + 2 * gid);
                pf2(g_P + (size_t)4 * NN * 64 + (size_t)sn1 * 64 + 2 * gid);
                pf2(g_P + (size_t)5 * NN * 64 + (size_t)dn1 * 64 + 2 * gid);
                pf2(g_P + (size_t)6 * NN * 64 + (size_t)sn1 * 64 + 2 * gid);
                pf2(g_P + (size_t)7 * NN * 64 + (size_t)dn1 * 64 + 2 * gid);
                if (en0 < (size_t)E) pf2(outEdge + en0 * 64 + 2 * gid);
                if (en1 < (size_t)E) pf2(outEdge + en1 * 64 + 2 * gid);
            }
            __syncwarp();

            #pragma unroll
            for (int nt = 0; nt < 8; nt++) {
                int c = 8 * nt + 2 * tig;
                *(float2*)(sSt + r0 * 68 + c) = make_float2(tf32r(silu_(acc[nt][0])), tf32r(silu_(acc[nt][1])));
                *(float2*)(sSt + r1 * 68 + c) = make_float2(tf32r(silu_(acc[nt][2])), tf32r(silu_(acc[nt][3])));
                acc[nt][0] = acc[nt][1] = acc[nt][2] = acc[nt][3] = 0.f;
            }
            __syncwarp();
            #pragma unroll 2
            for (int kt = 0; kt < 8; kt++) {
                int k0 = 8 * kt;
                unsigned a[4];
                a[0] = __float_as_uint(sSt[r0 * 68 + k0 + tig]);
                a[1] = __float_as_uint(sSt[r1 * 68 + k0 + tig]);
                a[2] = __float_as_uint(sSt[r0 * 68 + k0 + tig + 4]);
                a[3] = __float_as_uint(sSt[r1 * 68 + k0 + tig + 4]);
                const float* bp0 = sB2 + (k0 + tig) * 136 + gid;
                const float* bp1 = bp0 + 4 * 136;
                #pragma unroll
                for (int nt = 0; nt < 8; nt++) {
                    unsigned b[2] = { __float_as_uint(bp0[8 * nt]), __float_as_uint(bp1[8 * nt]) };
                    mma8(acc[nt], a, b);
                }
            }
            __syncwarp();
            #pragma unroll
            for (int nt = 8; nt < 16; nt++) {
                int c = 8 * (nt - 8) + 2 * tig;
                *(float2*)(sSt + r0 * 68 + c) = make_float2(tf32r(silu_(acc[nt][0])), tf32r(silu_(acc[nt][1])));
                *(float2*)(sSt + r1 * 68 + c) = make_float2(tf32r(silu_(acc[nt][2])), tf32r(silu_(acc[nt][3])));
                acc[nt][0] = acc[nt][1] = acc[nt][2] = acc[nt][3] = 0.f;
            }
            __syncwarp();
            #pragma unroll 2
            for (int kt = 0; kt < 8; kt++) {
                int k0 = 8 * kt;
                unsigned a[4];
                a[0] = __float_as_uint(sSt[r0 * 68 + k0 + tig]);
                a[1] = __float_as_uint(sSt[r1 * 68 + k0 + tig]);
                a[2] = __float_as_uint(sSt[r0 * 68 + k0 + tig + 4]);
                a[3] = __float_as_uint(sSt[r1 * 68 + k0 + tig + 4]);
                const float* bp0 = sB2 + (k0 + tig) * 136 + 64 + gid;
                const float* bp1 = bp0 + 4 * 136;
                #pragma unroll
                for (int nt = 8; nt < 16; nt++) {
                    unsigned b[2] = { __float_as_uint(bp0[8 * (nt - 8)]), __float_as_uint(bp1[8 * (nt - 8)]) };
                    mma8(acc[nt], a, b);
                }
            }

            float rb0[9], rb1[9];
            #pragma unroll
            for (int r = 0; r < 9; r++) {
                rb0[r] = v0 ? rbf[eg0 * 9 + r] : 0.f;
                rb1[r] = v1 ? rbf[eg1 * 9 + r] : 0.f;
            }
            #pragma unroll
            for (int nt = 0; nt < 8; nt++) {
                int c = 8 * nt + 2 * tig;
                float b2x = sBias[128 + c], b2y = sBias[128 + c + 1];
                float gbx = sBias[192 + c], gby = sBias[192 + c + 1];
                float h00 = silu_(acc[nt][0] + b2x), h01 = silu_(acc[nt][1] + b2y);
                float h10 = silu_(acc[nt][2] + b2x), h11 = silu_(acc[nt][3] + b2y);
                float g00 = sigm_(acc[nt + 8][0] + gbx), g01 = sigm_(acc[nt + 8][1] + gby);
                float g10 = sigm_(acc[nt + 8][2] + gbx), g11 = sigm_(acc[nt + 8][3] + gby);
                float wf00 = 0.f, wf01 = 0.f, wf10 = 0.f, wf11 = 0.f;
                #pragma unroll
                for (int r = 0; r < 9; r++) {
                    float2 wv = *(const float2*)(sWF + r * 64 + c);
                    wf00 += rb0[r] * wv.x; wf01 += rb0[r] * wv.y;
                    wf10 += rb1[r] * wv.x; wf11 += rb1[r] * wv.y;
                }
                if (v0) {
                    float2 swv = *(const float2*)(snw + eg0 * 64 + c);
                    red2(&g_agg[(size_t)d0 * 64 + c],
                         h00 * g00 * wf00 * swv.x, h01 * g01 * wf01 * swv.y);
                }
                if (v1) {
                    float2 swv = *(const float2*)(snw + eg1 * 64 + c);
                    red2(&g_agg[(size_t)d1 * 64 + c],
                         h10 * g10 * wf10 * swv.x, h11 * g11 * wf11 * swv.y);
                }
            }
            __syncwarp();
        }
    }
}

// ==================== node output ====================
__global__ __launch_bounds__(256) void nodeout_kernel(
    const float* __restrict__ nf, const float* __restrict__ Wout,
    float* __restrict__ out)
{
    __shared__ float sAG[4096];
    __shared__ float sW[4096];
    int tid = threadIdx.x;
    int m0 = blockIdx.x * 64;
    for (int i = tid; i < 1024; i += 256) {
        ((float4*)sW)[i] = ((const float4*)Wout)[i];
        int m = i >> 4;
        float4 v = make_float4(0.f, 0.f, 0.f, 0.f);
        if (m0 + m < NN) v = *(const float4*)&g_agg[(size_t)(m0 + m) * 64 + 4 * (i & 15)];
        ((float4*)sAG)[i] = v;
    }
    __syncthreads();
    int tx = tid & 15, ty = tid >> 4, n0 = 4 * tx;
    float acc[4][4] = {};
    #pragma unroll 16
    for (int k = 0; k < 64; k++) {
        float a0 = sAG[(4*ty+0)*64+k], a1 = sAG[(4*ty+1)*64+k];
        float a2 = sAG[(4*ty+2)*64+k], a3 = sAG[(4*ty+3)*64+k];
        float4 b = *(const float4*)&sW[k * 64 + n0];
        acc[0][0]+=a0*b.x; acc[0][1]+=a0*b.y; acc[0][2]+=a0*b.z; acc[0][3]+=a0*b.w;
        acc[1][0]+=a1*b.x; acc[1][1]+=a1*b.y; acc[1][2]+=a1*b.z; acc[1][3]+=a1*b.w;
        acc[2][0]+=a2*b.x; acc[2][1]+=a2*b.y; acc[2][2]+=a2*b.z; acc[2][3]+=a2*b.w;
        acc[3][0]+=a3*b.x; acc[3][1]+=a3*b.y; acc[3][2]+=a3*b.z; acc[3][3]+=a3*b.w;
    }
    #pragma unroll
    for (int i = 0; i < 4; i++) {
        int m = m0 + 4 * ty + i;
        if (m < NN) {
            float4 base = *(const float4*)&nf[(size_t)m * 64 + n0];
            *(float4*)&out[(size_t)m * 64 + n0] = make_float4(
                base.x + acc[i][0], base.y + acc[i][1], base.z + acc[i][2], base.w + acc[i][3]);
        }
    }
}

// ==================== launch ====================
extern "C" void kernel_launch(void* const* d_in, const int* in_sizes, int n_in,
                              void* d_out, int out_size) {
    const float* nf   = (const float*)d_in[0];
    const float* ef   = (const float*)d_in[1];
    const int*   src  = (const int*)d_in[2];
    const int*   dst  = (const int*)d_in[3];
    const float* rbf  = (const float*)d_in[4];
    const float* snw  = (const float*)d_in[5];
    const float* sew  = (const float*)d_in[6];
    const float* eW1  = (const float*)d_in[7];
    const float* eb1  = (const float*)d_in[8];
    const float* eW2  = (const float*)d_in[9];
    const float* eb2  = (const float*)d_in[10];
    const float* egW1 = (const float*)d_in[11];
    const float* egb1 = (const float*)d_in[12];
    const float* egW2 = (const float*)d_in[13];
    const float* egb2 = (const float*)d_in[14];
    const float* nW1  = (const float*)d_in[15];
    const float* nb1  = (const float*)d_in[16];
    const float* nW2  = (const float*)d_in[17];
    const float* nb2  = (const float*)d_in[18];
    const float* ngW1 = (const float*)d_in[19];
    const float* ngb1 = (const float*)d_in[20];
    const float* ngW2 = (const float*)d_in[21];
    const float* ngb2 = (const float*)d_in[22];
    const float* WoutM = (const float*)d_in[23];
    const float* nwf  = (const float*)d_in[24];
    const float* ewf  = (const float*)d_in[25];

    int E = in_sizes[2];
    float* outNode = (float*)d_out;
    float* outEdge = outNode + (size_t)NN * 64;

    const int FSM = 26944 * 4;
    const int PSM = 17408 * 4;
    static int configured = 0;
    if (!configured) {
        cudaFuncSetAttribute(fused_kernel, cudaFuncAttributeMaxDynamicSharedMemorySize, FSM);
        cudaFuncSetAttribute(proj_mma_kernel, cudaFuncAttributeMaxDynamicSharedMemorySize, PSM);
        configured = 1;
    }

    dim3 gP((NN + 127) / 128, 4);
    proj_mma_kernel<<<gP, 256, PSM>>>(nf, eW1, egW1, nW1, ngW1);

    int nTiles = (E + EPC - 1) / EPC;
    int grid = nTiles < GRID_F ? nTiles : GRID_F;
    fused_kernel<<<grid, 256, FSM>>>(
        ef, src, dst, rbf, sew, snw,
        eW1, eb1, eW2, eb2, egW1, egb1, egW2, egb2,
        nW1, nb1, nW2, nb2, ngW1, ngb1, ngW2, ngb2,
        ewf, nwf, outEdge, E, nTiles);

    nodeout_kernel<<<(NN + 63) / 64, 256>>>(nf, WoutM, outNode);
}